// round 17
// baseline (speedup 1.0000x reference)
#include <cuda_runtime.h>
#include <cuda_fp16.h>
#include <cstdint>

// Sinkhorn, linear domain, fp16-compressed kernel matrix, stage-buffered
// column sums (no init kernel; zeroing folded into build/final):
//   K = valid ? fp16(exp(m)) : 0      (built fused with Sinkhorn step 1, v0=1)
//   step t: u_i = 1 / sum_j K_ij * inv(sb[t-1]_j) ; sb[t]_j += sum_i K_ij u_i
//   out = valid ? u_i * exp(m_ij) * inv(sb[9]_j) : 0   (fp32 exp recompute)
//
// fused_pass hot loops run on the HFMA2 pipe: products k*v (and k*u)
// accumulate in fp16x2 registers (2 hfma2 per 4 halves instead of
// 4 cvt + 4 FFMA). u and v are scaled per block by powers of 2 so the max
// sits in [4,8) (products <= ~3.3e3, 8-term sums <= ~2.6e4 < 65504);
// subtotals convert to fp32 and descale exactly before use/atomics.
// u/v true values stay fp32 in global (they drift as (nc/nr)^t).

#define BB 64
#define NN 1024
#define MM 1024
#define NSTAGE 10

__device__ __half g_K[(size_t)BB * NN * MM];     // 128 MB scratch
__device__ float  g_u[BB * NN];
__device__ float  g_sb[NSTAGE][BB * MM];         // per-stage col-sum buffers

__device__ __forceinline__ float exp2i(int e) {  // exact 2^e
    return __int_as_float((e + 127) << 23);
}

// ---------------------------------------------------------------------------
// Build + Sinkhorn step 1 (v0 = 1): block = 32 rows x 8 warps x 4 rows.
// Also zeroes this block's slice of g_sb[9] for the NEXT replay.
// grid = (32, 64), block = 256.
// ---------------------------------------------------------------------------
__global__ void __launch_bounds__(256) build_fused_kernel(const float* __restrict__ m,
                                                          const int* __restrict__ nrows,
                                                          const int* __restrict__ ncols) {
    int b  = blockIdx.y;
    if (threadIdx.x < 32)
        g_sb[NSTAGE - 1][(b << 10) + blockIdx.x * 32 + threadIdx.x] = 0.f;

    int nr = nrows[b];
    int nc = ncols[b];
    int i0 = blockIdx.x * 32;
    if (i0 >= nr || nc == 0) return;
    int npass = (nc + 127) >> 7;   // 128-col tiles

    int lane = threadIdx.x & 31;
    int w    = threadIdx.x >> 5;

    float acc[32];
    #pragma unroll
    for (int k = 0; k < 32; k++) acc[k] = 0.f;

    const float* mb = m + ((size_t)b << 20);
    __half*      Kb = g_K + ((size_t)b << 20);

    #pragma unroll
    for (int q = 0; q < 4; q++) {
        int i = i0 + w * 4 + q;
        if (i < nr) {
            const float* mrow = mb + ((size_t)i << 10);
            __half*      krow = Kb + ((size_t)i << 10);
            uint2 kk[8];
            float s0 = 0.f, s1 = 0.f, s2 = 0.f, s3 = 0.f;
            #pragma unroll
            for (int p = 0; p < 8; p++) {
                if (p < npass) {
                    int j = p * 128 + lane * 4;
                    float4 mv = *reinterpret_cast<const float4*>(mrow + j);
                    float e0 = (j + 0 < nc) ? __expf(mv.x) : 0.f;
                    float e1 = (j + 1 < nc) ? __expf(mv.y) : 0.f;
                    float e2 = (j + 2 < nc) ? __expf(mv.z) : 0.f;
                    float e3 = (j + 3 < nc) ? __expf(mv.w) : 0.f;
                    __half2 h0 = __floats2half2_rn(e0, e1);
                    __half2 h1 = __floats2half2_rn(e2, e3);
                    kk[p].x = *reinterpret_cast<uint32_t*>(&h0);
                    kk[p].y = *reinterpret_cast<uint32_t*>(&h1);
                    *reinterpret_cast<uint2*>(krow + j) = kk[p];
                } else {
                    kk[p] = make_uint2(0u, 0u);
                }
                float2 f0 = __half22float2(*reinterpret_cast<__half2*>(&kk[p].x));
                float2 f1 = __half22float2(*reinterpret_cast<__half2*>(&kk[p].y));
                s0 += f0.x; s1 += f0.y; s2 += f1.x; s3 += f1.y;   // v0 = 1
            }
            float sum = (s0 + s1) + (s2 + s3);
            #pragma unroll
            for (int o = 16; o; o >>= 1) sum += __shfl_xor_sync(0xffffffffu, sum, o);
            float u = (sum > 0.f) ? __fdividef(1.0f, sum) : 0.f;
            if (lane == 0) g_u[(b << 10) + i] = u;
            #pragma unroll
            for (int p = 0; p < 8; p++) {
                float2 f0 = __half22float2(*reinterpret_cast<__half2*>(&kk[p].x));
                float2 f1 = __half22float2(*reinterpret_cast<__half2*>(&kk[p].y));
                acc[p * 4 + 0] = fmaf(f0.x, u, acc[p * 4 + 0]);
                acc[p * 4 + 1] = fmaf(f0.y, u, acc[p * 4 + 1]);
                acc[p * 4 + 2] = fmaf(f1.x, u, acc[p * 4 + 2]);
                acc[p * 4 + 3] = fmaf(f1.y, u, acc[p * 4 + 3]);
            }
        }
    }
    __shared__ float sm[8 * 1024];
    #pragma unroll
    for (int p = 0; p < 8; p++) {
        *reinterpret_cast<float4*>(&sm[w * 1024 + p * 128 + lane * 4]) =
            make_float4(acc[p * 4 + 0], acc[p * 4 + 1], acc[p * 4 + 2], acc[p * 4 + 3]);
    }
    __syncthreads();
    int t = threadIdx.x;
    int jmax = npass << 7;
    #pragma unroll
    for (int r = 0; r < 4; r++) {
        int j = r * 256 + t;
        if (j < jmax) {
            float s = 0.f;
            #pragma unroll
            for (int ww = 0; ww < 8; ww++) s += sm[ww * 1024 + j];
            atomicAdd(&g_sb[0][(b << 10) + j], s);
        }
    }
}

// ---------------------------------------------------------------------------
// Fused Sinkhorn step `stage` (1..9), HFMA2 two-phase version:
//   prologue: v = inv(sb[stage-1]); block vmax -> f; vh = fp16(v * 2^f)
//   phase 1: per warp row (4 rows), fp16x2 accumulate k*vh over tiles;
//            convert subtotals to fp32, reduce -> u = 2^f / S; g_u fp32
//   u-scale: block umax -> e; uh[q] = fp16x2(u * 2^e)
//   phase 2: per tile, fp16x2 accumulate k*uh over the 4 rows; convert,
//            descale by 2^-e, stage fp32 to smem
//   epilogue: cross-warp smem sum, one atomicAdd per column into sb[stage].
// grid = (32, 64), block = 256, 5 CTAs/SM.
// ---------------------------------------------------------------------------
__global__ void __launch_bounds__(256, 5) fused_pass_kernel(const int* __restrict__ nrows,
                                                            const int* __restrict__ ncols,
                                                            int stage) {
    int b  = blockIdx.y;
    int nr = nrows[b];
    int nc = ncols[b];
    int i0 = blockIdx.x * 32;
    if (i0 >= nr || nc == 0) return;
    int npass = (nc + 127) >> 7;      // 128-col tiles

    int lane = threadIdx.x & 31;
    int w    = threadIdx.x >> 5;
    int t    = threadIdx.x;

    __shared__ __align__(8) __half vh[1024];   // scaled fp16 column potentials
    __shared__ float sm[8 * 1024];             // per-warp column partial staging
    __shared__ float sred[9];                  // warp maxes + e broadcast

    // ---- prologue: v = 1/s, block vmax -> f, vh = fp16(v * 2^f) ----
    float fscale;
    {
        const float* s_in = &g_sb[stage - 1][b << 10];
        float4 s4 = *reinterpret_cast<const float4*>(s_in + t * 4);
        float v0 = (s4.x > 0.f) ? __fdividef(1.0f, s4.x) : 0.f;
        float v1 = (s4.y > 0.f) ? __fdividef(1.0f, s4.y) : 0.f;
        float v2 = (s4.z > 0.f) ? __fdividef(1.0f, s4.z) : 0.f;
        float v3 = (s4.w > 0.f) ? __fdividef(1.0f, s4.w) : 0.f;
        float vm = fmaxf(fmaxf(v0, v1), fmaxf(v2, v3));
        #pragma unroll
        for (int o = 16; o; o >>= 1) vm = fmaxf(vm, __shfl_xor_sync(0xffffffffu, vm, o));
        if (lane == 0) sred[w] = vm;
        __syncthreads();
        float vmax = sred[0];
        #pragma unroll
        for (int k = 1; k < 8; k++) vmax = fmaxf(vmax, sred[k]);
        int f = (vmax > 0.f) ? (2 - ilogbf(vmax)) : 0;   // vmax*2^f in [4,8)
        fscale = exp2i(f);
        __half2 h01 = __floats2half2_rn(v0 * fscale, v1 * fscale);
        __half2 h23 = __floats2half2_rn(v2 * fscale, v3 * fscale);
        *reinterpret_cast<__half2*>(&vh[t * 4])     = h01;
        *reinterpret_cast<__half2*>(&vh[t * 4 + 2]) = h23;
    }
    __syncthreads();

    const __half* Kb = g_K + ((size_t)b << 20);
    int ibase = i0 + w * 4;
    int nrow  = min(4, nr - ibase);   // may be <= 0; warp still does smem duties

    // ---- phase 1: row sums, fp16x2 accumulation ----
    __half2 hacc[4][2];
    #pragma unroll
    for (int q = 0; q < 4; q++) {
        hacc[q][0] = __floats2half2_rn(0.f, 0.f);
        hacc[q][1] = hacc[q][0];
    }
    for (int p = 0; p < npass; p++) {
        int j = (p << 7) + (lane << 2);
        __half2 v01 = *reinterpret_cast<const __half2*>(&vh[j]);
        __half2 v23 = *reinterpret_cast<const __half2*>(&vh[j + 2]);
        #pragma unroll
        for (int q = 0; q < 4; q++) {
            if (q < nrow) {
                uint2 kk = *reinterpret_cast<const uint2*>(
                    Kb + ((size_t)(ibase + q) << 10) + j);
                hacc[q][0] = __hfma2(*reinterpret_cast<__half2*>(&kk.x), v01, hacc[q][0]);
                hacc[q][1] = __hfma2(*reinterpret_cast<__half2*>(&kk.y), v23, hacc[q][1]);
            }
        }
    }
    float u[4];   // true fp32 u per row (identical across lanes after reduce)
    float umax = 0.f;
    #pragma unroll
    for (int q = 0; q < 4; q++) {
        float2 f0 = __half22float2(hacc[q][0]);
        float2 f1 = __half22float2(hacc[q][1]);
        float s = (f0.x + f0.y) + (f1.x + f1.y);
        #pragma unroll
        for (int o = 16; o; o >>= 1) s += __shfl_xor_sync(0xffffffffu, s, o);
        // s = rowsum * 2^f  =>  u = 2^f / s
        u[q] = (s > 0.f) ? (fscale * __fdividef(1.0f, s)) : 0.f;
        if (lane == 0 && q < nrow) g_u[(b << 10) + ibase + q] = u[q];
        umax = fmaxf(umax, u[q]);
    }

    // ---- block umax -> e; uh = fp16x2(u * 2^e) ----
    if (lane == 0) sred[w] = umax;
    __syncthreads();
    {
        float um = sred[0];
        #pragma unroll
        for (int k = 1; k < 8; k++) um = fmaxf(um, sred[k]);
        if (t == 0) sred[8] = (float)((um > 0.f) ? (2 - ilogbf(um)) : 0);
    }
    __syncthreads();
    int e = (int)sred[8];
    float escale  = exp2i(e);
    float descale = exp2i(-e);
    __half2 uh[4];
    #pragma unroll
    for (int q = 0; q < 4; q++) {
        float us = u[q] * escale;
        uh[q] = __floats2half2_rn(us, us);
    }

    // ---- phase 2: column partials, fp16x2 accumulation, fp32 staging ----
    for (int p = 0; p < npass; p++) {
        int j = (p << 7) + (lane << 2);
        __half2 c01 = __floats2half2_rn(0.f, 0.f);
        __half2 c23 = c01;
        #pragma unroll
        for (int q = 0; q < 4; q++) {
            if (q < nrow) {
                uint2 kk = *reinterpret_cast<const uint2*>(
                    Kb + ((size_t)(ibase + q) << 10) + j);
                c01 = __hfma2(*reinterpret_cast<__half2*>(&kk.x), uh[q], c01);
                c23 = __hfma2(*reinterpret_cast<__half2*>(&kk.y), uh[q], c23);
            }
        }
        float2 f0 = __half22float2(c01);
        float2 f1 = __half22float2(c23);
        *reinterpret_cast<float4*>(&sm[w * 1024 + j]) =
            make_float4(f0.x * descale, f0.y * descale,
                        f1.x * descale, f1.y * descale);
    }
    __syncthreads();

    // ---- epilogue: cross-warp sum + global atomic ----
    int jmax = npass << 7;
    float* s_out = &g_sb[stage][b << 10];
    #pragma unroll
    for (int r = 0; r < 4; r++) {
        int j = r * 256 + t;
        if (j < jmax) {
            float s = 0.f;
            #pragma unroll
            for (int ww = 0; ww < 8; ww++) s += sm[ww * 1024 + j];
            atomicAdd(&s_out[j], s);
        }
    }
}

// ---------------------------------------------------------------------------
// Final: out = valid ? u_i * exp(m_ij) * inv(sb[9]_j) : 0 — fp32 exp.
// Also re-zeroes g_sb[0..8] for the next graph replay.
// grid = 4096, block = 256, 16 float4/thread (full 256 MB write).
// ---------------------------------------------------------------------------
__global__ void final_kernel(const float* __restrict__ m,
                             const int* __restrict__ nrows,
                             const int* __restrict__ ncols,
                             float* __restrict__ out) {
    {
        int z = blockIdx.x * 256 + threadIdx.x;
        const int ztot = (NSTAGE - 1) * BB * MM;
        if (z < ztot) (&g_sb[0][0])[z] = 0.f;
    }

    int b   = blockIdx.x >> 6;
    int sub = blockIdx.x & 63;
    int nr = nrows[b];
    int nc = ncols[b];
    const float* mb = m + ((size_t)b << 20);
    float*       ob = out + ((size_t)b << 20);
    const float* sb = &g_sb[NSTAGE - 1][b << 10];

    #pragma unroll
    for (int k = 0; k < 16; k++) {
        int q = sub * 4096 + k * 256 + threadIdx.x;
        int i = q >> 8;
        int j = (q & 255) << 2;
        float4 o;
        if (i >= nr || j >= nc) {
            o = make_float4(0.f, 0.f, 0.f, 0.f);
        } else {
            float4 mm = *reinterpret_cast<const float4*>(mb + ((size_t)q << 2));
            float  u  = g_u[(b << 10) + i];
            float4 s4 = *reinterpret_cast<const float4*>(sb + j);
            float vx = (s4.x > 0.f) ? __fdividef(1.0f, s4.x) : 0.f;
            float vy = (s4.y > 0.f) ? __fdividef(1.0f, s4.y) : 0.f;
            float vz = (s4.z > 0.f) ? __fdividef(1.0f, s4.z) : 0.f;
            float vw = (s4.w > 0.f) ? __fdividef(1.0f, s4.w) : 0.f;
            o.x = __expf(mm.x) * u * vx;
            o.y = __expf(mm.y) * u * vy;
            o.z = __expf(mm.z) * u * vz;
            o.w = __expf(mm.w) * u * vw;
        }
        *reinterpret_cast<float4*>(ob + ((size_t)q << 2)) = o;
    }
}

extern "C" void kernel_launch(void* const* d_in, const int* in_sizes, int n_in,
                              void* d_out, int out_size) {
    const float* m     = (const float*)d_in[0];
    const int*   nrows = (const int*)d_in[1];
    const int*   ncols = (const int*)d_in[2];
    float* out = (float*)d_out;

    build_fused_kernel<<<dim3(32, 64), 256>>>(m, nrows, ncols);    // step 1 (+zero sb[9])
    for (int t = 1; t <= 9; t++)                                   // steps 2..10
        fused_pass_kernel<<<dim3(32, 64), 256>>>(nrows, ncols, t);
    final_kernel<<<4096, 256>>>(m, nrows, ncols, out);             // out (+zero sb[0..8])
}